// round 12
// baseline (speedup 1.0000x reference)
#include <cuda_runtime.h>
#include <math.h>

// Fixed problem shapes
#define BB    8
#define NA    5
#define NC    8
#define NH    192
#define NW    192
#define TT    50
#define ATTRS 15                 // 7 + NC
#define NHW   (NH*NW)            // 36864
#define CELLS (BB*NA*NHW)        // 1,474,560
#define NT    (BB*TT)            // 400
#define NIGN  (NT*NA)            // 2000
#define NPAIR (BB*TT*TT)         // 20000 ordered pairs

#define TPB       256
#define CPT       4
#define NB_SPARSE 4
#define NB_DENSE  (CELLS/(CPT*TPB))       // 1440 (exact)
#define NB_TOTAL  (NB_SPARSE+NB_DENSE)    // 1444
#define SP_THREADS (NB_SPARSE*TPB)        // 1024
#define HASH_SZ   4096
#define HASH_MASK (HASH_SZ-1)
#define NWARP     (TPB/32)

typedef unsigned long long u64;

// ---- persistent device scratch (finisher resets -> replay-safe) ----
__device__ double   g_S0 = 0.0;
__device__ float    g_crA[7];               // accumulated via REDG.F32 by sparse blocks
__device__ int      g_nObjG, g_removedG;    // accumulated
__device__ unsigned g_ticket = 0;
__device__ unsigned g_sbar[3];              // quad spin barriers
__device__ unsigned g_gen = 1;              // hash generation
__device__ u64      g_hash[HASH_SZ];        // gen<<32 | cell (zero-init: gen0 invalid)
__device__ int      g_meta[NT];
__device__ unsigned char g_loser[NT];

__device__ __forceinline__ float sp_fast(float v) {   // softplus == bce0 (clip never binds, |v|<16)
    return fmaxf(v, 0.f) + __logf(1.f + __expf(-fabsf(v)));
}
__device__ __forceinline__ float sigf(float v) {
    return 1.f / (1.f + __expf(-v));
}
__device__ __forceinline__ unsigned hash_cell(int cell) {
    return (((unsigned)cell * 2654435761u) >> 16) & HASH_MASK;
}

// generation-tagged global hash insert; true iff this thread claimed the cell
__device__ __forceinline__ bool hash_insert(int cell, unsigned gen) {
    const u64 want = ((u64)gen << 32) | (unsigned)cell;
    volatile u64* vh = (volatile u64*)g_hash;
    unsigned h = hash_cell(cell);
    while (true) {
        u64 cur = vh[h];
        if (cur == want) return false;              // present (obj or dup)
        if ((unsigned)(cur >> 32) == gen) { h = (h + 1) & HASH_MASK; continue; }
        u64 prev = atomicCAS(&g_hash[h], cur, want);
        if (prev == cur) return true;               // claimed
    }
}

// barrier among the 4 sparse blocks (all wave-1 resident -> no deadlock)
__device__ __forceinline__ void quad_barrier(int idx, int tid, unsigned gen) {
    __syncthreads();
    if (tid == 0) {
        __threadfence();
        atomicAdd(&g_sbar[idx], 1u);
        volatile unsigned* vb = (volatile unsigned*)&g_sbar[idx];
        unsigned target = 4u * gen;                  // not reset between replays; gen-scaled
        while (*vb < target) { }
    }
    __syncthreads();
}

__global__ void __launch_bounds__(TPB)
fused(const float* __restrict__ x,
      const float* __restrict__ tg,
      const float* __restrict__ anchors,
      float* __restrict__ out)
{
    __shared__ float s_red[NWARP][8];
    __shared__ int   s_cnt[2];

    const int tid  = threadIdx.x;
    const int bid  = blockIdx.x;
    const int lane = tid & 31;
    const int wid  = tid >> 5;

    if (bid >= NB_SPARSE) {
        // ========== dense: softplus sum over conf channel (R11-proven shape) ==========
        int c0 = ((bid - NB_SPARSE) * TPB + tid) * CPT;
        int i0 = c0 % NW;
        int j  = (c0 / NW) % NH;
        int ba = c0 / NHW;
        float4 v = *(const float4*)(x + ((size_t)ba * ATTRS + 6) * NHW + (size_t)j * NW + i0);
        float local = sp_fast(v.x) + sp_fast(v.y) + sp_fast(v.z) + sp_fast(v.w);

        #pragma unroll
        for (int o = 16; o; o >>= 1) local += __shfl_down_sync(0xffffffffu, local, o);
        if (lane == 0) s_red[wid][0] = local;
        __syncthreads();
        if (tid == 0) {
            float bs = 0.f;
            #pragma unroll
            for (int w = 0; w < NWARP; w++) bs += s_red[w][0];
            atomicAdd(&g_S0, (double)bs);
        }
    } else {
        // ========== sparse: 4 cooperating blocks, 1024 threads total ==========
        const int gtid = bid * TPB + tid;           // 0..1023
        const unsigned gen = *(volatile unsigned*)&g_gen;
        float a0 = 0.f, a1 = 0.f, a2 = 0.f, a3 = 0.f, a4 = 0.f, a5 = 0.f, a6 = 0.f;
        float r_fx = 0.f, r_fy = 0.f, r_tw = 0.f, r_th = 0.f;
        int   r_label = 0;
        float aw_[NA], ah_[NA];
        #pragma unroll
        for (int a = 0; a < NA; a++) { aw_[a] = anchors[2*a]; ah_[a] = anchors[2*a+1]; }
        if (tid < 2) s_cnt[tid] = 0;

        volatile int* vmeta = (volatile int*)g_meta;
        volatile unsigned char* vloser = (volatile unsigned char*)g_loser;

        // phase 0: one thread per target
        if (gtid < NT) {
            const int t = gtid;
            vloser[t] = 0;
            const float* r = tg + (size_t)t * 5;
            float r0 = r[0], r1 = r[1], r2 = r[2], r3 = r[3], r4 = r[4];
            int valid = ((r0 + r1 + r2 + r3 + r4) != 0.f);
            float gx = r1 * NW, gy = r2 * NH, gw = r3 * NW, gh = r4 * NH;
            int gi = (int)floorf(gx), gj = (int)floorf(gy);
            float bestIou = -1.f; int best = 0; float awb = 1.f, ahb = 1.f;
            #pragma unroll
            for (int a = 0; a < NA; a++) {
                float inter = fminf(gw, aw_[a]) * fminf(gh, ah_[a]);
                float iou   = inter / (gw * gh + aw_[a] * ah_[a] - inter);
                if (iou > bestIou) { bestIou = iou; best = a; awb = aw_[a]; ahb = ah_[a]; }
            }
            vmeta[t] = (valid << 28) | (best << 16) | (gj << 8) | gi;
            r_label = (int)r0;
            r_fx = gx - floorf(gx);
            r_fy = gy - floorf(gy);
            r_tw = __logf(gw / awb + 1e-16f);
            r_th = __logf(gh / ahb + 1e-16f);
        }
        quad_barrier(0, tid, gen);

        // phase 0.5: parallel last-write-wins via pair comparisons
        for (int p = gtid; p < NPAIR; p += SP_THREADS) {
            int b  = p / (TT*TT);
            int r  = p - b * (TT*TT);
            int ti = r / TT;
            int tj = r - ti * TT;
            if (tj > ti) {
                int t1 = b * TT + ti, t2 = b * TT + tj;
                int m1 = vmeta[t1];
                if ((m1 >> 28) && m1 == vmeta[t2]) vloser[t1] = 1;  // benign race
            }
        }
        quad_barrier(1, tid, gen);

        // phase 1: winners -> hash insert + obj-cell work
        if (gtid < NT) {
            const int t = gtid;
            int meta = vmeta[t];
            if ((meta >> 28) && !vloser[t]) {
                int b = t / TT;
                int best = (meta >> 16) & 0xff, gj = (meta >> 8) & 0xff, gi = meta & 0xff;
                int cell = ((b * NA + best) * NH + gj) * NW + gi;
                hash_insert(cell, gen);             // winners unique -> claims
                atomicAdd(&s_cnt[0], 1);

                size_t base = (size_t)(b * NA + best) * ATTRS * NHW + (size_t)gj * NW + gi;
                float x0 = x[base];
                float x1 = x[base + (size_t)NHW];
                float x2 = x[base + 2 * (size_t)NHW];
                float x3 = x[base + 3 * (size_t)NHW];
                float xc = x[base + 6 * (size_t)NHW];

                float dx = sigf(x0) - r_fx;
                float dy = sigf(x1) - r_fy;
                float dw = x2 - r_tw;
                float dh = x3 - r_th;
                a2 += dx * dx;
                a3 += dy * dy;
                a4 += dw * dw;
                a5 += dh * dh;
                a1 += sp_fast(-xc);                 // -log p (tconf=1 bce)
                a0 -= sp_fast(xc);                  // remove bce0 from noobj sum

                float sv[NC]; float m = -1e30f;
                #pragma unroll
                for (int c = 0; c < NC; c++) {
                    sv[c] = sigf(x[base + (size_t)(7 + c) * NHW]);
                    m = fmaxf(m, sv[c]);
                }
                float sum = 0.f;
                #pragma unroll
                for (int c = 0; c < NC; c++) sum += __expf(sv[c] - m);
                a6 += m + __logf(sum) - sv[r_label];
            }
        }
        quad_barrier(2, tid, gen);   // all obj cells inserted before ignore probes

        // phase 2: ignore cells (iou > 0.6); dedup via hash; obj beats ignore
        for (int k = gtid; k < NIGN; k += SP_THREADS) {
            int t = k / NA, a = k - (k / NA) * NA;
            int meta = vmeta[t];
            if (!(meta >> 28)) continue;
            float gw = tg[(size_t)t * 5 + 3] * NW;
            float gh = tg[(size_t)t * 5 + 4] * NH;
            float inter = fminf(gw, aw_[a]) * fminf(gh, ah_[a]);
            float iou   = inter / (gw * gh + aw_[a] * ah_[a] - inter);
            if (!(iou > 0.6f)) continue;
            int b = t / TT, gj = (meta >> 8) & 0xff, gi = meta & 0xff;
            int cell = ((b * NA + a) * NH + gj) * NW + gi;
            if (!hash_insert(cell, gen)) continue;  // dup or obj cell
            atomicAdd(&s_cnt[1], 1);
            float xc = x[((size_t)(b * NA + a) * ATTRS + 6) * NHW + (size_t)gj * NW + gi];
            a0 -= sp_fast(xc);
        }

        // block reduction in float -> global accumulators
        #pragma unroll
        for (int o = 16; o; o >>= 1) {
            a0 += __shfl_down_sync(0xffffffffu, a0, o);
            a1 += __shfl_down_sync(0xffffffffu, a1, o);
            a2 += __shfl_down_sync(0xffffffffu, a2, o);
            a3 += __shfl_down_sync(0xffffffffu, a3, o);
            a4 += __shfl_down_sync(0xffffffffu, a4, o);
            a5 += __shfl_down_sync(0xffffffffu, a5, o);
            a6 += __shfl_down_sync(0xffffffffu, a6, o);
        }
        if (lane == 0) {
            s_red[wid][0] = a0; s_red[wid][1] = a1; s_red[wid][2] = a2;
            s_red[wid][3] = a3; s_red[wid][4] = a4; s_red[wid][5] = a5;
            s_red[wid][6] = a6;
        }
        __syncthreads();
        if (tid == 0) {
            float c[7] = {0,0,0,0,0,0,0};
            #pragma unroll
            for (int w = 0; w < NWARP; w++)
                #pragma unroll
                for (int i = 0; i < 7; i++) c[i] += s_red[w][i];
            #pragma unroll
            for (int i = 0; i < 7; i++) atomicAdd(&g_crA[i], c[i]);
            atomicAdd(&g_nObjG, s_cnt[0]);
            atomicAdd(&g_removedG, s_cnt[0] + s_cnt[1]);
        }
    }

    // ========== ticket: last of ALL 1444 blocks finalizes ==========
    __syncthreads();
    if (tid == 0) {
        __threadfence();
        unsigned old = atomicAdd(&g_ticket, 1u);
        if (old == (unsigned)(NB_TOTAL - 1)) {
            double S0   = atomicAdd(&g_S0, 0.0) + (double)*(volatile float*)&g_crA[0];
            double nobj = (double)*(volatile int*)&g_nObjG;
            double cnt  = (double)CELLS - (double)*(volatile int*)&g_removedG;
            double objs = (double)*(volatile float*)&g_crA[2] + (double)*(volatile float*)&g_crA[3]
                        + (double)*(volatile float*)&g_crA[4] + (double)*(volatile float*)&g_crA[5]
                        + (double)*(volatile float*)&g_crA[1]
                        + (double)*(volatile float*)&g_crA[6] / (double)BB;
            out[0] = (float)(objs / nobj + S0 / cnt);
            // replay-safe resets
            g_S0 = 0.0;
            g_ticket = 0u;
            #pragma unroll
            for (int i = 0; i < 7; i++) g_crA[i] = 0.f;
            g_nObjG = 0; g_removedG = 0;
            g_gen = *(volatile unsigned*)&g_gen + 1u;   // invalidates hash + rescales barriers
        }
    }
}

extern "C" void kernel_launch(void* const* d_in, const int* in_sizes, int n_in,
                              void* d_out, int out_size) {
    const float* x  = (const float*)d_in[0];
    const float* tg = (const float*)d_in[1];
    const float* an = (const float*)d_in[2];
    fused<<<NB_TOTAL, TPB>>>(x, tg, an, (float*)d_out);
}

// round 13
// speedup vs baseline: 1.4517x; 1.4517x over previous
#include <cuda_runtime.h>
#include <math.h>

// Fixed problem shapes
#define BB    8
#define NA    5
#define NC    8
#define NH    192
#define NW    192
#define TT    50
#define ATTRS 15                 // 7 + NC
#define NHW   (NH*NW)            // 36864
#define CELLS (BB*NA*NHW)        // 1,474,560

#define TPB       256
#define CPT       4
#define NB_SPARSE BB                      // one block per batch
#define NB_DENSE  (CELLS/(CPT*TPB))       // 1440 (exact)
#define NB_TOTAL  (NB_SPARSE+NB_DENSE)    // 1448
#define HASH_SZ   512                     // per-batch: <=300 inserts
#define HASH_MASK (HASH_SZ-1)
#define NWARP     (TPB/32)

// ---- persistent device scratch (finisher resets -> replay-safe) ----
__device__ double   g_S0 = 0.0;
__device__ float    g_crA[7];            // 0:noobjCorr 1:objconf 2..5:coords 6:ce
__device__ int      g_nObjG, g_removedG;
__device__ unsigned g_ticket = 0;

__device__ __forceinline__ float sp_fast(float v) {   // softplus == bce0 (clip never binds, |v|<16)
    return fmaxf(v, 0.f) + __logf(1.f + __expf(-fabsf(v)));
}
__device__ __forceinline__ float sigf(float v) {
    return 1.f / (1.f + __expf(-v));
}
__device__ __forceinline__ unsigned hash_cell(int cell) {
    return (((unsigned)cell * 2654435761u) >> 16) & HASH_MASK;
}

__global__ void __launch_bounds__(TPB)
fused(const float* __restrict__ x,
      const float* __restrict__ tg,
      const float* __restrict__ anchors,
      float* __restrict__ out)
{
    __shared__ float s_red[NWARP][8];            // both paths use
    // sparse-only (small: ~3KB total, no occupancy tax)
    __shared__ int   s_hash[HASH_SZ];
    __shared__ int   s_meta[TT];                 // valid<<28 | best<<16 | gj<<8 | gi
    __shared__ unsigned char s_loser[TT];
    __shared__ float s_gw[TT], s_gh[TT];
    __shared__ int   s_cnt[2];                   // nObj, removed(claims)
    __shared__ float s_anchor[2*NA];

    const int tid  = threadIdx.x;
    const int bid  = blockIdx.x;
    const int lane = tid & 31;
    const int wid  = tid >> 5;

    if (bid >= NB_SPARSE) {
        // ========== dense: softplus sum over conf channel (proven shape) ==========
        int c0 = ((bid - NB_SPARSE) * TPB + tid) * CPT;
        int i0 = c0 % NW;
        int j  = (c0 / NW) % NH;
        int ba = c0 / NHW;
        float4 v = *(const float4*)(x + ((size_t)ba * ATTRS + 6) * NHW + (size_t)j * NW + i0);
        float local = sp_fast(v.x) + sp_fast(v.y) + sp_fast(v.z) + sp_fast(v.w);

        #pragma unroll
        for (int o = 16; o; o >>= 1) local += __shfl_down_sync(0xffffffffu, local, o);
        if (lane == 0) s_red[wid][0] = local;
        __syncthreads();
        if (tid == 0) {
            float bs = 0.f;
            #pragma unroll
            for (int w = 0; w < NWARP; w++) bs += s_red[w][0];
            atomicAdd(&g_S0, (double)bs);        // REDG.F64
        }
    } else {
        // ========== sparse: one block per batch, fully independent ==========
        const int b = bid;
        float a0 = 0.f, a1 = 0.f, a2 = 0.f, a3 = 0.f, a4 = 0.f, a5 = 0.f, a6 = 0.f;
        float r_fx = 0.f, r_fy = 0.f, r_tw = 0.f, r_th = 0.f;
        int   r_label = 0;

        for (int i = tid; i < HASH_SZ; i += TPB) s_hash[i] = -1;
        if (tid < TT) s_loser[tid] = 0;
        if (tid < 2)  s_cnt[tid] = 0;
        if (tid < 2*NA) s_anchor[tid] = anchors[tid];
        __syncthreads();

        // phase 0: one thread per target (this batch's 50 targets)
        if (tid < TT) {
            const int t = b * TT + tid;
            const float* r = tg + (size_t)t * 5;
            float r0 = r[0], r1 = r[1], r2 = r[2], r3 = r[3], r4 = r[4];
            int valid = ((r0 + r1 + r2 + r3 + r4) != 0.f);
            float gx = r1 * NW, gy = r2 * NH, gw = r3 * NW, gh = r4 * NH;
            int gi = (int)floorf(gx), gj = (int)floorf(gy);
            float bestIou = -1.f; int best = 0; float awb = 1.f, ahb = 1.f;
            #pragma unroll
            for (int a = 0; a < NA; a++) {
                float aw = s_anchor[2*a], ah = s_anchor[2*a+1];
                float inter = fminf(gw, aw) * fminf(gh, ah);
                float iou   = inter / (gw * gh + aw * ah - inter);
                if (iou > bestIou) { bestIou = iou; best = a; awb = aw; ahb = ah; }
            }
            s_meta[tid] = (valid << 28) | (best << 16) | (gj << 8) | gi;
            s_gw[tid] = gw; s_gh[tid] = gh;
            r_label = (int)r0;
            r_fx = gx - floorf(gx);
            r_fy = gy - floorf(gy);
            r_tw = __logf(gw / awb + 1e-16f);
            r_th = __logf(gh / ahb + 1e-16f);
        }
        __syncthreads();

        // phase 0.5: last-write-wins within this batch (2500 pairs, 10 iters)
        for (int p = tid; p < TT*TT; p += TPB) {
            int ti = p / TT, tj = p - (p / TT) * TT;
            if (tj > ti) {
                int m1 = s_meta[ti];
                if ((m1 >> 28) && m1 == s_meta[tj]) s_loser[ti] = 1;   // benign race
            }
        }
        __syncthreads();

        // phase 1+2 MERGED (obj/ignore corrections are order-free; dedup via claim):
        // obj: winners do coords/CE/objconf always, and claim their cell for the
        //      union correction; ignore entries claim too — first claimer subtracts.
        if (tid < TT) {
            int meta = s_meta[tid];
            if ((meta >> 28) && !s_loser[tid]) {
                int best = (meta >> 16) & 0xff, gj = (meta >> 8) & 0xff, gi = meta & 0xff;
                int cell = ((b * NA + best) * NH + gj) * NW + gi;
                // claim for union
                unsigned h = hash_cell(cell);
                bool mine = false;
                while (true) {
                    int prev = atomicCAS(&s_hash[h], -1, cell);
                    if (prev == -1)   { mine = true; break; }
                    if (prev == cell) break;
                    h = (h + 1) & HASH_MASK;
                }
                atomicAdd(&s_cnt[0], 1);            // nObj (winners are distinct cells)

                size_t base = (size_t)(b * NA + best) * ATTRS * NHW + (size_t)gj * NW + gi;
                float x0 = x[base];
                float x1 = x[base + (size_t)NHW];
                float x2 = x[base + 2 * (size_t)NHW];
                float x3 = x[base + 3 * (size_t)NHW];
                float xc = x[base + 6 * (size_t)NHW];

                float dx = sigf(x0) - r_fx;
                float dy = sigf(x1) - r_fy;
                float dw = x2 - r_tw;
                float dh = x3 - r_th;
                a2 += dx * dx;
                a3 += dy * dy;
                a4 += dw * dw;
                a5 += dh * dh;
                a1 += sp_fast(-xc);                 // -log p (tconf=1)
                if (mine) { a0 -= sp_fast(xc); atomicAdd(&s_cnt[1], 1); }

                float sv[NC]; float m = -1e30f;
                #pragma unroll
                for (int c = 0; c < NC; c++) {
                    sv[c] = sigf(x[base + (size_t)(7 + c) * NHW]);
                    m = fmaxf(m, sv[c]);
                }
                float sum = 0.f;
                #pragma unroll
                for (int c = 0; c < NC; c++) sum += __expf(sv[c] - m);
                a6 += m + __logf(sum) - sv[r_label];
            }
        }
        if (tid < TT * NA) {                        // 250 ignore candidates, same phase
            int tl = tid / NA, a = tid - (tid / NA) * NA;
            int meta = s_meta[tl];
            if (meta >> 28) {
                float gw = s_gw[tl], gh = s_gh[tl];
                float aw = s_anchor[2*a], ah = s_anchor[2*a+1];
                float inter = fminf(gw, aw) * fminf(gh, ah);
                float iou   = inter / (gw * gh + aw * ah - inter);
                if (iou > 0.6f) {
                    int gj = (meta >> 8) & 0xff, gi = meta & 0xff;
                    int cell = ((b * NA + a) * NH + gj) * NW + gi;
                    unsigned h = hash_cell(cell);
                    bool mine = false;
                    while (true) {
                        int prev = atomicCAS(&s_hash[h], -1, cell);
                        if (prev == -1)   { mine = true; break; }
                        if (prev == cell) break;       // already claimed (obj or dup)
                        h = (h + 1) & HASH_MASK;
                    }
                    if (mine) {
                        atomicAdd(&s_cnt[1], 1);
                        float xc = x[((size_t)(b * NA + a) * ATTRS + 6) * NHW
                                     + (size_t)gj * NW + gi];
                        a0 -= sp_fast(xc);
                    }
                }
            }
        }

        // block reduction in float -> global accumulators
        #pragma unroll
        for (int o = 16; o; o >>= 1) {
            a0 += __shfl_down_sync(0xffffffffu, a0, o);
            a1 += __shfl_down_sync(0xffffffffu, a1, o);
            a2 += __shfl_down_sync(0xffffffffu, a2, o);
            a3 += __shfl_down_sync(0xffffffffu, a3, o);
            a4 += __shfl_down_sync(0xffffffffu, a4, o);
            a5 += __shfl_down_sync(0xffffffffu, a5, o);
            a6 += __shfl_down_sync(0xffffffffu, a6, o);
        }
        if (lane == 0) {
            s_red[wid][0] = a0; s_red[wid][1] = a1; s_red[wid][2] = a2;
            s_red[wid][3] = a3; s_red[wid][4] = a4; s_red[wid][5] = a5;
            s_red[wid][6] = a6;
        }
        __syncthreads();
        if (tid == 0) {
            float c[7] = {0,0,0,0,0,0,0};
            #pragma unroll
            for (int w = 0; w < NWARP; w++)
                #pragma unroll
                for (int i = 0; i < 7; i++) c[i] += s_red[w][i];
            #pragma unroll
            for (int i = 0; i < 7; i++) atomicAdd(&g_crA[i], c[i]);
            atomicAdd(&g_nObjG, s_cnt[0]);
            atomicAdd(&g_removedG, s_cnt[1]);
        }
    }

    // ========== ticket: last of all 1448 blocks finalizes ==========
    __syncthreads();
    if (tid == 0) {
        __threadfence();
        unsigned old = atomicAdd(&g_ticket, 1u);
        if (old == (unsigned)(NB_TOTAL - 1)) {
            double S0   = atomicAdd(&g_S0, 0.0) + (double)*(volatile float*)&g_crA[0];
            double nobj = (double)*(volatile int*)&g_nObjG;
            double cnt  = (double)CELLS - (double)*(volatile int*)&g_removedG;
            double objs = (double)*(volatile float*)&g_crA[2] + (double)*(volatile float*)&g_crA[3]
                        + (double)*(volatile float*)&g_crA[4] + (double)*(volatile float*)&g_crA[5]
                        + (double)*(volatile float*)&g_crA[1]
                        + (double)*(volatile float*)&g_crA[6] / (double)BB;
            out[0] = (float)(objs / nobj + S0 / cnt);
            // replay-safe resets
            g_S0 = 0.0;
            g_ticket = 0u;
            #pragma unroll
            for (int i = 0; i < 7; i++) g_crA[i] = 0.f;
            g_nObjG = 0; g_removedG = 0;
        }
    }
}

extern "C" void kernel_launch(void* const* d_in, const int* in_sizes, int n_in,
                              void* d_out, int out_size) {
    const float* x  = (const float*)d_in[0];
    const float* tg = (const float*)d_in[1];
    const float* an = (const float*)d_in[2];
    fused<<<NB_TOTAL, TPB>>>(x, tg, an, (float*)d_out);
}

// round 14
// speedup vs baseline: 2.2843x; 1.5735x over previous
#include <cuda_runtime.h>
#include <math.h>

// Fixed problem shapes
#define BB    8
#define NA    5
#define NC    8
#define NH    192
#define NW    192
#define TT    50
#define ATTRS 15                 // 7 + NC
#define NHW   (NH*NW)            // 36864
#define CELLS (BB*NA*NHW)        // 1,474,560

#define TPB       256
#define CPT       8
#define NB_SPARSE BB                      // one block per batch
#define NB_DENSE  (CELLS/(CPT*TPB))       // 720 (exact)
#define NB_TOTAL  (NB_SPARSE+NB_DENSE)    // 728
#define HASH_SZ   512                     // per-batch: <=300 inserts
#define HASH_MASK (HASH_SZ-1)
#define NWARP     (TPB/32)

// ---- persistent device scratch (finisher resets -> replay-safe) ----
__device__ float    g_S0 = 0.f;
__device__ float    g_crA[7];            // 0:noobjCorr 1:objconf 2..5:coords 6:ce
__device__ int      g_nObjG, g_removedG;
__device__ unsigned g_ticket = 0;

__device__ __forceinline__ float sp_fast(float v) {   // softplus == bce0 (clip never binds, |v|<16)
    return fmaxf(v, 0.f) + __logf(1.f + __expf(-fabsf(v)));
}
__device__ __forceinline__ float sigf(float v) {
    return 1.f / (1.f + __expf(-v));
}
__device__ __forceinline__ unsigned hash_cell(int cell) {
    return (((unsigned)cell * 2654435761u) >> 16) & HASH_MASK;
}

__global__ void __launch_bounds__(TPB)
fused(const float* __restrict__ x,
      const float* __restrict__ tg,
      const float* __restrict__ anchors,
      float* __restrict__ out)
{
    __shared__ float s_red[NWARP][8];
    // sparse-only (~3KB, no occupancy tax)
    __shared__ int   s_hash[HASH_SZ];
    __shared__ int   s_meta[TT];                 // valid<<28 | best<<16 | gj<<8 | gi
    __shared__ unsigned char s_loser[TT];
    __shared__ float s_gw[TT], s_gh[TT];
    __shared__ int   s_cnt[2];
    __shared__ float s_anchor[2*NA];

    const int tid  = threadIdx.x;
    const int bid  = blockIdx.x;
    const int lane = tid & 31;
    const int wid  = tid >> 5;

    if (bid >= NB_SPARSE) {
        // ========== dense: 8 cells/thread, streamlined addressing ==========
        int c0 = ((bid - NB_SPARSE) * TPB + tid) * CPT;
        int ba = c0 / NHW;                        // magic-mul division
        const float* p = x + (size_t)c0 + (size_t)(6 + 14 * ba) * NHW;
        float4 A = *(const float4*)p;
        float4 B = *(const float4*)(p + 4);       // independent -> MLP=2
        float local = (sp_fast(A.x) + sp_fast(A.y)) + (sp_fast(A.z) + sp_fast(A.w))
                    + (sp_fast(B.x) + sp_fast(B.y)) + (sp_fast(B.z) + sp_fast(B.w));

        #pragma unroll
        for (int o = 16; o; o >>= 1) local += __shfl_down_sync(0xffffffffu, local, o);
        if (lane == 0) s_red[wid][0] = local;
        __syncthreads();
        if (tid == 0) {
            float bs = 0.f;
            #pragma unroll
            for (int w = 0; w < NWARP; w++) bs += s_red[w][0];
            atomicAdd(&g_S0, bs);                 // REDG.F32
        }
    } else {
        // ========== sparse: one block per batch (R13-proven) ==========
        const int b = bid;
        float a0 = 0.f, a1 = 0.f, a2 = 0.f, a3 = 0.f, a4 = 0.f, a5 = 0.f, a6 = 0.f;
        float r_fx = 0.f, r_fy = 0.f, r_tw = 0.f, r_th = 0.f;
        int   r_label = 0;

        for (int i = tid; i < HASH_SZ; i += TPB) s_hash[i] = -1;
        if (tid < TT) s_loser[tid] = 0;
        if (tid < 2)  s_cnt[tid] = 0;
        if (tid < 2*NA) s_anchor[tid] = anchors[tid];
        __syncthreads();

        // phase 0: one thread per target
        if (tid < TT) {
            const int t = b * TT + tid;
            const float* r = tg + (size_t)t * 5;
            float r0 = r[0], r1 = r[1], r2 = r[2], r3 = r[3], r4 = r[4];
            int valid = ((r0 + r1 + r2 + r3 + r4) != 0.f);
            float gx = r1 * NW, gy = r2 * NH, gw = r3 * NW, gh = r4 * NH;
            int gi = (int)floorf(gx), gj = (int)floorf(gy);
            float bestIou = -1.f; int best = 0; float awb = 1.f, ahb = 1.f;
            #pragma unroll
            for (int a = 0; a < NA; a++) {
                float aw = s_anchor[2*a], ah = s_anchor[2*a+1];
                float inter = fminf(gw, aw) * fminf(gh, ah);
                float iou   = inter / (gw * gh + aw * ah - inter);
                if (iou > bestIou) { bestIou = iou; best = a; awb = aw; ahb = ah; }
            }
            s_meta[tid] = (valid << 28) | (best << 16) | (gj << 8) | gi;
            s_gw[tid] = gw; s_gh[tid] = gh;
            r_label = (int)r0;
            r_fx = gx - floorf(gx);
            r_fy = gy - floorf(gy);
            r_tw = __logf(gw / awb + 1e-16f);
            r_th = __logf(gh / ahb + 1e-16f);
        }
        __syncthreads();

        // phase 0.5: last-write-wins within this batch
        for (int p = tid; p < TT*TT; p += TPB) {
            int ti = p / TT, tj = p - (p / TT) * TT;
            if (tj > ti) {
                int m1 = s_meta[ti];
                if ((m1 >> 28) && m1 == s_meta[tj]) s_loser[ti] = 1;   // benign race
            }
        }
        __syncthreads();

        // phase 1+2 merged: union correction is order-free (same -bce0 either way)
        if (tid < TT) {
            int meta = s_meta[tid];
            if ((meta >> 28) && !s_loser[tid]) {
                int best = (meta >> 16) & 0xff, gj = (meta >> 8) & 0xff, gi = meta & 0xff;
                int cell = ((b * NA + best) * NH + gj) * NW + gi;
                unsigned h = hash_cell(cell);
                bool mine = false;
                while (true) {
                    int prev = atomicCAS(&s_hash[h], -1, cell);
                    if (prev == -1)   { mine = true; break; }
                    if (prev == cell) break;
                    h = (h + 1) & HASH_MASK;
                }
                atomicAdd(&s_cnt[0], 1);

                // issue ALL scattered loads first (one DRAM round trip)
                const float* bp = x + (size_t)(b * NA + best) * ATTRS * NHW
                                    + (size_t)gj * NW + gi;
                float x0 = bp[0];
                float x1 = bp[(size_t)NHW];
                float x2 = bp[2 * (size_t)NHW];
                float x3 = bp[3 * (size_t)NHW];
                float xc = bp[6 * (size_t)NHW];
                float sv[NC];
                #pragma unroll
                for (int c = 0; c < NC; c++) sv[c] = bp[(size_t)(7 + c) * NHW];

                float dx = sigf(x0) - r_fx;
                float dy = sigf(x1) - r_fy;
                float dw = x2 - r_tw;
                float dh = x3 - r_th;
                a2 += dx * dx;
                a3 += dy * dy;
                a4 += dw * dw;
                a5 += dh * dh;
                a1 += sp_fast(-xc);                 // -log p (tconf=1)
                if (mine) { a0 -= sp_fast(xc); atomicAdd(&s_cnt[1], 1); }

                float m = -1e30f;
                #pragma unroll
                for (int c = 0; c < NC; c++) { sv[c] = sigf(sv[c]); m = fmaxf(m, sv[c]); }
                float sum = 0.f;
                #pragma unroll
                for (int c = 0; c < NC; c++) sum += __expf(sv[c] - m);
                a6 += m + __logf(sum) - sv[r_label];
            }
        }
        if (tid < TT * NA) {                        // 250 ignore candidates
            int tl = tid / NA, a = tid - (tid / NA) * NA;
            int meta = s_meta[tl];
            if (meta >> 28) {
                float gw = s_gw[tl], gh = s_gh[tl];
                float aw = s_anchor[2*a], ah = s_anchor[2*a+1];
                float inter = fminf(gw, aw) * fminf(gh, ah);
                float iou   = inter / (gw * gh + aw * ah - inter);
                if (iou > 0.6f) {
                    int gj = (meta >> 8) & 0xff, gi = meta & 0xff;
                    int cell = ((b * NA + a) * NH + gj) * NW + gi;
                    unsigned h = hash_cell(cell);
                    bool mine = false;
                    while (true) {
                        int prev = atomicCAS(&s_hash[h], -1, cell);
                        if (prev == -1)   { mine = true; break; }
                        if (prev == cell) break;       // claimed (obj or dup)
                        h = (h + 1) & HASH_MASK;
                    }
                    if (mine) {
                        atomicAdd(&s_cnt[1], 1);
                        float xc = x[((size_t)(b * NA + a) * ATTRS + 6) * NHW
                                     + (size_t)gj * NW + gi];
                        a0 -= sp_fast(xc);
                    }
                }
            }
        }

        // block reduction in float -> global accumulators
        #pragma unroll
        for (int o = 16; o; o >>= 1) {
            a0 += __shfl_down_sync(0xffffffffu, a0, o);
            a1 += __shfl_down_sync(0xffffffffu, a1, o);
            a2 += __shfl_down_sync(0xffffffffu, a2, o);
            a3 += __shfl_down_sync(0xffffffffu, a3, o);
            a4 += __shfl_down_sync(0xffffffffu, a4, o);
            a5 += __shfl_down_sync(0xffffffffu, a5, o);
            a6 += __shfl_down_sync(0xffffffffu, a6, o);
        }
        if (lane == 0) {
            s_red[wid][0] = a0; s_red[wid][1] = a1; s_red[wid][2] = a2;
            s_red[wid][3] = a3; s_red[wid][4] = a4; s_red[wid][5] = a5;
            s_red[wid][6] = a6;
        }
        __syncthreads();
        if (tid == 0) {
            float c[7] = {0,0,0,0,0,0,0};
            #pragma unroll
            for (int w = 0; w < NWARP; w++)
                #pragma unroll
                for (int i = 0; i < 7; i++) c[i] += s_red[w][i];
            #pragma unroll
            for (int i = 0; i < 7; i++) atomicAdd(&g_crA[i], c[i]);
            atomicAdd(&g_nObjG, s_cnt[0]);
            atomicAdd(&g_removedG, s_cnt[1]);
        }
    }

    // ========== ticket: last of all 728 blocks finalizes ==========
    __syncthreads();
    if (tid == 0) {
        __threadfence();
        unsigned old = atomicAdd(&g_ticket, 1u);
        if (old == (unsigned)(NB_TOTAL - 1)) {
            double S0   = (double)*(volatile float*)&g_S0 + (double)*(volatile float*)&g_crA[0];
            double nobj = (double)*(volatile int*)&g_nObjG;
            double cnt  = (double)CELLS - (double)*(volatile int*)&g_removedG;
            double objs = (double)*(volatile float*)&g_crA[2] + (double)*(volatile float*)&g_crA[3]
                        + (double)*(volatile float*)&g_crA[4] + (double)*(volatile float*)&g_crA[5]
                        + (double)*(volatile float*)&g_crA[1]
                        + (double)*(volatile float*)&g_crA[6] / (double)BB;
            out[0] = (float)(objs / nobj + S0 / cnt);
            // replay-safe resets
            g_S0 = 0.f;
            g_ticket = 0u;
            #pragma unroll
            for (int i = 0; i < 7; i++) g_crA[i] = 0.f;
            g_nObjG = 0; g_removedG = 0;
        }
    }
}

extern "C" void kernel_launch(void* const* d_in, const int* in_sizes, int n_in,
                              void* d_out, int out_size) {
    const float* x  = (const float*)d_in[0];
    const float* tg = (const float*)d_in[1];
    const float* an = (const float*)d_in[2];
    fused<<<NB_TOTAL, TPB>>>(x, tg, an, (float*)d_out);
}